// round 8
// baseline (speedup 1.0000x reference)
#include <cuda_runtime.h>
#include <cstdint>

#define T_LEN   1000000
#define HIDDEN  75
#define NS      16
#define BS      160                // steps per checkpoint block (1e6/160 = 6250)
#define NBLK    (T_LEN / BS)       // 6250
#define RB      4                  // ring blocks (smem), power of 2

// Scratch: negated log-priors (np = -prior), natural order; 8-state checkpoints p0..p7.
__device__ float g_np[T_LEN * 16];     // 64 MB
__device__ float g_ckpt[NBLK * 8];     // 200 KB

__device__ __forceinline__ int ld_acq(const int* p) {
    int v;
    asm volatile("ld.acquire.cta.b32 %0, [%1];" : "=r"(v) : "l"(p) : "memory");
    return v;
}
__device__ __forceinline__ void st_rel(int* p, int v) {
    asm volatile("st.release.cta.b32 [%0], %1;" :: "l"(p), "r"(v) : "memory");
}
// fl(np*1.0 + p) == fl(np + p) bitwise; FFMA with immediate multiplier issues at
// rt_SMSP=1 on the fma pipe (2x the FADD rate) — this is the whole point.
__device__ __forceinline__ float fadd_via_ffma_imm(float np, float p) {
    float r;
    asm("fma.rn.f32 %0, %1, 0f3F800000, %2;" : "=f"(r) : "f"(np), "f"(p));
    return r;
}

// ================= K1: priors =================
// Replays reference op order: mul+add+relu, fma-accumulate ascending j,
// +b2, max, shift, sequential exp-sum, log. Stores NEGATED log_softmax (natural order).
__global__ void k_priors(const float* __restrict__ rx,
                         const float* __restrict__ W1,
                         const float* __restrict__ b1,
                         const float* __restrict__ W2,
                         const float* __restrict__ b2,
                         int T) {
    __shared__ float sW1[HIDDEN], sb1[HIDDEN], sW2[HIDDEN * NS], sb2[NS];
    for (int i = threadIdx.x; i < HIDDEN; i += blockDim.x) { sW1[i] = W1[i]; sb1[i] = b1[i]; }
    for (int i = threadIdx.x; i < HIDDEN * NS; i += blockDim.x) sW2[i] = W2[i];
    if (threadIdx.x < NS) sb2[threadIdx.x] = b2[threadIdx.x];
    __syncthreads();

    int t = blockIdx.x * blockDim.x + threadIdx.x;
    if (t >= T) return;

    float x = rx[t];
    float acc[NS];
#pragma unroll
    for (int i = 0; i < NS; i++) acc[i] = 0.0f;

    for (int j = 0; j < HIDDEN; j++) {
        float h = __fadd_rn(__fmul_rn(x, sW1[j]), sb1[j]);
        h = fmaxf(h, 0.0f);
#pragma unroll
        for (int i = 0; i < NS; i++) acc[i] = fmaf(h, sW2[j * NS + i], acc[i]);
    }
#pragma unroll
    for (int i = 0; i < NS; i++) acc[i] = __fadd_rn(acc[i], sb2[i]);

    float m = acc[0];
#pragma unroll
    for (int i = 1; i < NS; i++) m = fmaxf(m, acc[i]);

    float sh[NS];
    float s = 0.0f;
#pragma unroll
    for (int i = 0; i < NS; i++) {
        sh[i] = __fadd_rn(acc[i], -m);
        s = __fadd_rn(s, expf(sh[i]));
    }
    float L = logf(s);

    float* dst = g_np + (size_t)t * NS;
#pragma unroll
    for (int i = 0; i < NS; i++) dst[i] = __fadd_rn(L, -sh[i]);   // -prior, natural order
}

// ================= K2: exact sequential scan =================
// Warp 0: 8 scalar states s0..s7. Per step:
//   v_j = FFMA(np_j, 1.0imm, p)   (16x, fma pipe at rt1)
//   s_i = fminf(v_even, v_odd)    (8x FMNMX, alu pipe)
//   + 4x LDS.128 for the 16 priors.
// Warps 1-3: stage priors global->smem ring (own SMSPs; spins steal no scan slots).
__global__ void __launch_bounds__(128, 1) k_scan() {
    __shared__ __align__(16) float ring[RB * BS * 16];   // 40 KB
    __shared__ int flag[RB];
    __shared__ int consumed;

    const int tid  = threadIdx.x;
    const int wid  = tid >> 5;
    const int lane = tid & 31;

    if (tid < RB) flag[tid] = 0;
    if (tid == 0) consumed = 0;
    __syncthreads();

    if (wid == 0) {
        float s0 = 0.f, s1 = 0.f, s2 = 0.f, s3 = 0.f, s4 = 0.f, s5 = 0.f, s6 = 0.f, s7 = 0.f;
        for (int b = 0; b < NBLK; b++) {
            if (lane == 0) {
                float4* cp = (float4*)(g_ckpt + (size_t)b * 8);
                cp[0] = make_float4(s0, s1, s2, s3);
                cp[1] = make_float4(s4, s5, s6, s7);
            }
            while (ld_acq(&flag[b & (RB - 1)]) != b + 1) { }
            const float4* b4 = (const float4*)&ring[(b & (RB - 1)) * (BS * 16)];
#pragma unroll 1
            for (int kk = 0; kk < BS; kk += 16) {
#pragma unroll
                for (int k2 = 0; k2 < 16; k2++) {
                    const int k = kk + k2;
                    const float4 e0 = b4[k * 4 + 0];   // np0..3
                    const float4 e1 = b4[k * 4 + 1];   // np4..7
                    const float4 e2 = b4[k * 4 + 2];   // np8..11
                    const float4 e3 = b4[k * 4 + 3];   // np12..15
                    float v0  = fadd_via_ffma_imm(e0.x, s0);
                    float v1  = fadd_via_ffma_imm(e0.y, s1);
                    float v2  = fadd_via_ffma_imm(e0.z, s2);
                    float v3  = fadd_via_ffma_imm(e0.w, s3);
                    float v4  = fadd_via_ffma_imm(e1.x, s4);
                    float v5  = fadd_via_ffma_imm(e1.y, s5);
                    float v6  = fadd_via_ffma_imm(e1.z, s6);
                    float v7  = fadd_via_ffma_imm(e1.w, s7);
                    float v8  = fadd_via_ffma_imm(e2.x, s0);
                    float v9  = fadd_via_ffma_imm(e2.y, s1);
                    float v10 = fadd_via_ffma_imm(e2.z, s2);
                    float v11 = fadd_via_ffma_imm(e2.w, s3);
                    float v12 = fadd_via_ffma_imm(e3.x, s4);
                    float v13 = fadd_via_ffma_imm(e3.y, s5);
                    float v14 = fadd_via_ffma_imm(e3.z, s6);
                    float v15 = fadd_via_ffma_imm(e3.w, s7);
                    s0 = fminf(v0,  v1);
                    s1 = fminf(v2,  v3);
                    s2 = fminf(v4,  v5);
                    s3 = fminf(v6,  v7);
                    s4 = fminf(v8,  v9);
                    s5 = fminf(v10, v11);
                    s6 = fminf(v12, v13);
                    s7 = fminf(v14, v15);
                }
            }
            if (lane == 0) st_rel(&consumed, b + 1);
        }
    } else {
        // copier warps: wid 1..3 handle blocks b with b % 3 == wid-1
        for (int b = wid - 1; b < NBLK; b += 3) {
            while (b >= RB && ld_acq(&consumed) < b - RB + 1) __nanosleep(100);
            const float4* src = (const float4*)(g_np + (size_t)b * (BS * 16));
            float4* dst = (float4*)&ring[(b & (RB - 1)) * (BS * 16)];
#pragma unroll
            for (int r = 0; r < (BS * 16 / 4) / 32; r++)   // 20 iterations
                dst[r * 32 + lane] = src[r * 32 + lane];
            __syncwarp();
            if (lane == 0) st_rel(&flag[b & (RB - 1)], b + 1);
        }
    }
}

// ================= K3: parallel det/conf emission =================
// Each thread replays one BS-step chunk bit-exactly from its checkpoint.
__global__ void k_emit(float* __restrict__ out_det, float* __restrict__ out_conf) {
    int c = blockIdx.x * blockDim.x + threadIdx.x;
    if (c >= NBLK) return;

    float p[8];
    float4 a = *(const float4*)(g_ckpt + (size_t)c * 8);
    float4 b = *(const float4*)(g_ckpt + (size_t)c * 8 + 4);
    p[0] = a.x; p[1] = a.y; p[2] = a.z; p[3] = a.w;
    p[4] = b.x; p[5] = b.y; p[6] = b.z; p[7] = b.w;

    const float* np = g_np + (size_t)c * (BS * 16);
    const int tbase = c * BS;

    for (int k = 0; k < BS; k++) {
        // det: first-index argmin over p[0..7], parity
        float best = p[0];
        int idx = 0;
#pragma unroll
        for (int j = 1; j < 8; j++) {
            if (p[j] < best) { best = p[j]; idx = j; }
        }
        // conf: S = sum over 16 duplicated exps, sequential ascending; 2*conf = 2/S
        float e[8];
#pragma unroll
        for (int j = 0; j < 8; j++) e[j] = expf(__fadd_rn(best, -p[j]));
        float S = e[0];
#pragma unroll
        for (int j = 1; j < 8; j++) S = __fadd_rn(S, e[j]);
#pragma unroll
        for (int j = 0; j < 8; j++) S = __fadd_rn(S, e[j]);
        float conf = __fdiv_rn(1.0f, S);

        out_det[tbase + k]  = (float)(idx & 1);
        out_conf[tbase + k] = __fmul_rn(2.0f, conf);

        // update (bit-identical arithmetic to K2: fl(p+np) then fminf)
        const float* q = np + k * 16;
        float4 q0 = *(const float4*)(q);
        float4 q1 = *(const float4*)(q + 4);
        float4 q2 = *(const float4*)(q + 8);
        float4 q3 = *(const float4*)(q + 12);
        float nv[16] = { q0.x, q0.y, q0.z, q0.w,  q1.x, q1.y, q1.z, q1.w,
                         q2.x, q2.y, q2.z, q2.w,  q3.x, q3.y, q3.z, q3.w };
        float newp[8];
#pragma unroll
        for (int i = 0; i < 8; i++) {
            int a2 = (2 * i) & 7;
            newp[i] = fminf(__fadd_rn(p[a2],     nv[2 * i]),
                            __fadd_rn(p[a2 + 1], nv[2 * i + 1]));
        }
#pragma unroll
        for (int i = 0; i < 8; i++) p[i] = newp[i];
    }
}

// ================= launch =================
extern "C" void kernel_launch(void* const* d_in, const int* in_sizes, int n_in,
                              void* d_out, int out_size) {
    const float* rx = (const float*)d_in[0];
    const float* W1 = (const float*)d_in[1];
    const float* b1 = (const float*)d_in[2];
    const float* W2 = (const float*)d_in[3];
    const float* b2 = (const float*)d_in[4];
    float* out = (float*)d_out;

    int T = in_sizes[0];
    if (T > T_LEN) T = T_LEN;

    k_priors<<<(T + 255) / 256, 256>>>(rx, W1, b1, W2, b2, T);
    k_scan<<<1, 128>>>();
    k_emit<<<(NBLK + 127) / 128, 128>>>(out, out + T);
}